// round 4
// baseline (speedup 1.0000x reference)
#include <cuda_runtime.h>
#include <math.h>

#define Bc   4
#define Tc   2048
#define Cc   2048
#define Hc   16
#define HKVc 4
#define Dc   128
#define Mrows (Bc*Tc)          // 8192
#define KVC  (HKVc*Dc)         // 512

// ---------------- scratch (device globals; no runtime allocation) -----------
__device__ float g_q [(size_t)Mrows*Cc];   // [b,t,h,d]
__device__ float g_k [(size_t)Mrows*KVC];  // [b,t,hkv,d]
__device__ float g_v [(size_t)Mrows*KVC];
__device__ float g_ao[(size_t)Mrows*Cc];   // attention output [b,t,h,d]

// ---------------- fp32 SGEMM, C[m,n] = sum_k A[m,k]*B[n,k] (NT) -------------
// BM=BN=128, BK=16, 256 threads, 8x8 microtile with stride-16 column/row map.
#define GBM 128
#define GBN 128
#define GBK 16
#define GPAD 129

__global__ void __launch_bounds__(256, 2)
sgemm_nt(const float* __restrict__ A, const float* __restrict__ Bm,
         float* __restrict__ Cm, int N, int K)
{
    __shared__ float As[GBK][GPAD];
    __shared__ float Bs[GBK][GPAD];

    const int tid = threadIdx.x;
    const int bm = blockIdx.y * GBM;
    const int bn = blockIdx.x * GBN;
    const int tx = tid & 15;
    const int ty = tid >> 4;

    float acc[8][8];
#pragma unroll
    for (int i = 0; i < 8; i++)
#pragma unroll
        for (int j = 0; j < 8; j++) acc[i][j] = 0.f;

    for (int k0 = 0; k0 < K; k0 += GBK) {
#pragma unroll
        for (int l = 0; l < 2; l++) {
            int f   = tid + l * 256;          // 0..511
            int row = f >> 2;                 // 0..127
            int c4  = (f & 3) << 2;           // 0,4,8,12
            float4 va = *(const float4*)(A  + (size_t)(bm + row) * K + k0 + c4);
            As[c4+0][row] = va.x; As[c4+1][row] = va.y;
            As[c4+2][row] = va.z; As[c4+3][row] = va.w;
            float4 vb = *(const float4*)(Bm + (size_t)(bn + row) * K + k0 + c4);
            Bs[c4+0][row] = vb.x; Bs[c4+1][row] = vb.y;
            Bs[c4+2][row] = vb.z; Bs[c4+3][row] = vb.w;
        }
        __syncthreads();
#pragma unroll
        for (int k = 0; k < GBK; k++) {
            float a[8], b[8];
#pragma unroll
            for (int i = 0; i < 8; i++) a[i] = As[k][ty + 16*i];
#pragma unroll
            for (int j = 0; j < 8; j++) b[j] = Bs[k][tx + 16*j];
#pragma unroll
            for (int i = 0; i < 8; i++)
#pragma unroll
                for (int j = 0; j < 8; j++)
                    acc[i][j] += a[i] * b[j];
        }
        __syncthreads();
    }

#pragma unroll
    for (int i = 0; i < 8; i++) {
        float* crow = Cm + (size_t)(bm + ty + 16*i) * N + bn;
#pragma unroll
        for (int j = 0; j < 8; j++)
            crow[tx + 16*j] = acc[i][j];
    }
}

// ---------------- RoPE (NeoX rotate-half), in place -------------------------
__global__ void rope_kernel(float* __restrict__ p, const float* __restrict__ freqs, int nh)
{
    int idx = blockIdx.x * blockDim.x + threadIdx.x;   // exact grid, no bounds check
    int pr = idx & 63;
    int h  = (idx >> 6) % nh;
    int bt = idx / (64 * nh);
    int t  = bt & (Tc - 1);
    float c = freqs[(t * 64 + pr) * 2 + 0];
    float s = freqs[(t * 64 + pr) * 2 + 1];
    float* base = p + ((size_t)bt * nh + h) * Dc;
    float u0 = base[pr], u1 = base[pr + 64];
    base[pr]      = u0 * c - u1 * s;
    base[pr + 64] = u1 * c + u0 * s;
}

// ---------------- flash attention (causal, GQA g=4), fp32 -------------------
// block = (qtile 64 rows, head, batch); 256 threads.
// smem: Qst[128][65] (d-major), Kst[128][65], Vs[64][128], Ss[64][67], stats.
#define QPAD 65
#define SPAD 67
#define ATT_SMEM_FLOATS (128*QPAD*2 + 64*128 + 64*SPAD + 128)
#define ATT_SMEM_BYTES  (ATT_SMEM_FLOATS * 4)

__global__ void __launch_bounds__(256, 1)
attn_kernel(const float* __restrict__ q, const float* __restrict__ k,
            const float* __restrict__ v, float* __restrict__ o)
{
    extern __shared__ float sm[];
    float* Qst   = sm;                     // [128][65]   Qst[d][r]
    float* Kst   = Qst + 128 * QPAD;       // [128][65]   Kst[d][c]
    float* Vs    = Kst + 128 * QPAD;       // [64][128]   Vs[c][d]
    float* Ss    = Vs  + 64 * 128;         // [64][67]
    float* row_f = Ss  + 64 * SPAD;        // [64] rescale
    float* row_l = row_f + 64;             // [64] denom

    const int qt = blockIdx.x, h = blockIdx.y, b = blockIdx.z;
    const int kvh = h >> 2;
    const int tid = threadIdx.x;
    const int wid = tid >> 5, lane = tid & 31;
    const int lr = lane >> 4, lc = lane & 15;
    const int tr = tid >> 4,  tc = tid & 15;
    const float qscale = 0.08838834764831845f;  // 1/sqrt(128)

    // ---- load Q tile, transposed + pre-scaled ----
#pragma unroll
    for (int it = 0; it < 4; it++) {
        int r = it * 16 + wid * 2 + lr;
        int t = qt * 64 + r;
        const float* gq = q + (((size_t)(b * Tc + t)) * Hc + h) * Dc;
#pragma unroll
        for (int dit = 0; dit < 2; dit++) {
            int d = lc * 4 + dit * 64;
            float4 val = *(const float4*)(gq + d);
            Qst[(d+0)*QPAD + r] = val.x * qscale;
            Qst[(d+1)*QPAD + r] = val.y * qscale;
            Qst[(d+2)*QPAD + r] = val.z * qscale;
            Qst[(d+3)*QPAD + r] = val.w * qscale;
        }
    }

    float Oa[4][8];
#pragma unroll
    for (int i = 0; i < 4; i++)
#pragma unroll
        for (int j = 0; j < 8; j++) Oa[i][j] = 0.f;

    float m_r = -1e30f, l_r = 0.f;   // row stats, owned by threads 0..63

    for (int kt = 0; kt <= qt; kt++) {
        // ---- load K (transposed) and V (row-major) tiles ----
#pragma unroll
        for (int it = 0; it < 4; it++) {
            int c0 = it * 16 + wid * 2 + lr;
            int t  = kt * 64 + c0;
            const float* gk = k + (((size_t)(b * Tc + t)) * HKVc + kvh) * Dc;
            const float* gv = v + (((size_t)(b * Tc + t)) * HKVc + kvh) * Dc;
#pragma unroll
            for (int dit = 0; dit < 2; dit++) {
                int d = lc * 4 + dit * 64;
                float4 kv4 = *(const float4*)(gk + d);
                Kst[(d+0)*QPAD + c0] = kv4.x;
                Kst[(d+1)*QPAD + c0] = kv4.y;
                Kst[(d+2)*QPAD + c0] = kv4.z;
                Kst[(d+3)*QPAD + c0] = kv4.w;
                float4 vv4 = *(const float4*)(gv + d);
                *(float4*)(Vs + c0 * 128 + d) = vv4;
            }
        }
        __syncthreads();

        // ---- phase A: S = Q K^T (4x4 microtile, stride-16 map) ----
        float accS[4][4];
#pragma unroll
        for (int i = 0; i < 4; i++)
#pragma unroll
            for (int j = 0; j < 4; j++) accS[i][j] = 0.f;
#pragma unroll 8
        for (int kk = 0; kk < 128; kk++) {
            float a[4], bb[4];
#pragma unroll
            for (int i = 0; i < 4; i++) a[i]  = Qst[kk*QPAD + tr + 16*i];
#pragma unroll
            for (int j = 0; j < 4; j++) bb[j] = Kst[kk*QPAD + tc + 16*j];
#pragma unroll
            for (int i = 0; i < 4; i++)
#pragma unroll
                for (int j = 0; j < 4; j++)
                    accS[i][j] += a[i] * bb[j];
        }
        if (kt == qt) {
#pragma unroll
            for (int i = 0; i < 4; i++)
#pragma unroll
                for (int j = 0; j < 4; j++)
                    if (tc + 16*j > tr + 16*i) accS[i][j] = -1e30f;
        }
#pragma unroll
        for (int i = 0; i < 4; i++)
#pragma unroll
            for (int j = 0; j < 4; j++)
                Ss[(tr + 16*i)*SPAD + tc + 16*j] = accS[i][j];
        __syncthreads();

        // ---- phase B: online softmax row update (threads 0..63) ----
        if (tid < 64) {
            const int r = tid;
            float mnew = m_r;
#pragma unroll 8
            for (int j = 0; j < 64; j++) mnew = fmaxf(mnew, Ss[r*SPAD + j]);
            float f = __expf(m_r - mnew);
            float s = 0.f;
#pragma unroll 8
            for (int j = 0; j < 64; j++) {
                float e = __expf(Ss[r*SPAD + j] - mnew);
                Ss[r*SPAD + j] = e;
                s += e;
            }
            l_r = l_r * f + s;
            m_r = mnew;
            row_f[r] = f;
            row_l[r] = l_r;
        }
        __syncthreads();

        // ---- phase C: O = O*f + P V (4x8 microtile) ----
#pragma unroll
        for (int i = 0; i < 4; i++) {
            float f = row_f[tr + 16*i];
#pragma unroll
            for (int j = 0; j < 8; j++) Oa[i][j] *= f;
        }
#pragma unroll 4
        for (int jj = 0; jj < 64; jj++) {
            float p[4], vv[8];
#pragma unroll
            for (int i = 0; i < 4; i++) p[i]  = Ss[(tr + 16*i)*SPAD + jj];
#pragma unroll
            for (int j = 0; j < 8; j++) vv[j] = Vs[jj*128 + tc + 16*j];
#pragma unroll
            for (int i = 0; i < 4; i++)
#pragma unroll
                for (int j = 0; j < 8; j++)
                    Oa[i][j] += p[i] * vv[j];
        }
        __syncthreads();
    }

    // ---- epilogue: normalize and store ----
#pragma unroll
    for (int i = 0; i < 4; i++) {
        int r = tr + 16*i;
        float linv = 1.f / row_l[r];
        int t = qt * 64 + r;
        float* go = o + (((size_t)(b * Tc + t)) * Hc + h) * Dc;
#pragma unroll
        for (int j = 0; j < 8; j++)
            go[tc + 16*j] = Oa[i][j] * linv;
    }
}

// ---------------- host launcher ---------------------------------------------
extern "C" void kernel_launch(void* const* d_in, const int* in_sizes, int n_in,
                              void* d_out, int out_size)
{
    (void)in_sizes; (void)n_in; (void)out_size;
    const float* x     = (const float*)d_in[0];
    const float* freqs = (const float*)d_in[1];
    const float* Wq    = (const float*)d_in[2];
    const float* Wk    = (const float*)d_in[3];
    const float* Wv    = (const float*)d_in[4];
    const float* Wo    = (const float*)d_in[5];
    float* out = (float*)d_out;

    float *q, *k, *v, *ao;
    cudaGetSymbolAddress((void**)&q,  g_q);
    cudaGetSymbolAddress((void**)&k,  g_k);
    cudaGetSymbolAddress((void**)&v,  g_v);
    cudaGetSymbolAddress((void**)&ao, g_ao);

    cudaFuncSetAttribute(attn_kernel,
                         cudaFuncAttributeMaxDynamicSharedMemorySize,
                         ATT_SMEM_BYTES);

    dim3 blk(256);

    // projections: q = x@Wq^T, k = x@Wk^T, v = x@Wv^T
    sgemm_nt<<<dim3(Cc  / GBN, Mrows / GBM), blk>>>(x, Wq, q,  Cc,  Cc);
    sgemm_nt<<<dim3(KVC / GBN, Mrows / GBM), blk>>>(x, Wk, k,  KVC, Cc);
    sgemm_nt<<<dim3(KVC / GBN, Mrows / GBM), blk>>>(x, Wv, v,  KVC, Cc);

    // RoPE (in place)
    rope_kernel<<<(Mrows * Hc   * 64) / 256, 256>>>(q, freqs, Hc);
    rope_kernel<<<(Mrows * HKVc * 64) / 256, 256>>>(k, freqs, HKVc);

    // causal GQA flash attention
    attn_kernel<<<dim3(Tc / 64, Hc, Bc), blk, ATT_SMEM_BYTES>>>(q, k, v, ao);

    // output projection: out = ao @ Wo^T
    sgemm_nt<<<dim3(Cc / GBN, Mrows / GBM), blk>>>(ao, Wo, out, Cc, Cc);
}

// round 5
// speedup vs baseline: 2.9419x; 2.9419x over previous
#include <cuda_runtime.h>
#include <math.h>

#define Bc   4
#define Tc   2048
#define Cc   2048
#define Hc   16
#define HKVc 4
#define Dc   128
#define Mrows (Bc*Tc)          // 8192
#define KVC  (HKVc*Dc)         // 512

// ---------------- scratch (device globals; no runtime allocation) -----------
__device__ float g_q [(size_t)Mrows*Cc];   // [b,t,h,d]
__device__ float g_k [(size_t)Mrows*KVC];  // [b,t,hkv,d]
__device__ float g_v [(size_t)Mrows*KVC];
__device__ float g_ao[(size_t)Mrows*Cc];   // attention output [b,t,h,d]

// ---------------- tf32 helpers ----------------------------------------------
__device__ __forceinline__ unsigned f2tf(float x) {
    unsigned u;
    asm("cvt.rna.tf32.f32 %0, %1;" : "=r"(u) : "f"(x));
    return u;
}

// D = A(16x8, row) * B(8x8, col) + D, tf32 in, fp32 out
__device__ __forceinline__ void mma_tf32(float* d, const unsigned* a, const unsigned* b) {
    asm volatile(
        "mma.sync.aligned.m16n8k8.row.col.f32.tf32.tf32.f32 "
        "{%0,%1,%2,%3},{%4,%5,%6,%7},{%8,%9},{%0,%1,%2,%3};"
        : "+f"(d[0]), "+f"(d[1]), "+f"(d[2]), "+f"(d[3])
        : "r"(a[0]), "r"(a[1]), "r"(a[2]), "r"(a[3]), "r"(b[0]), "r"(b[1]));
}

// ---------------- tf32 GEMM, C[m,n] = sum_k A[m,k]*B[n,k] (NT) ---------------
// 128x128 block tile, BK=16, 128 threads (4 warps, 2x2 grid of 64x64 warp tiles)
#define GLD 20   // smem row pitch (floats): conflict-free for frag loads + STS

__global__ void __launch_bounds__(128, 2)
gemm_tf32_nt(const float* __restrict__ A, const float* __restrict__ Bm,
             float* __restrict__ Cm, int N, int K)
{
    __shared__ unsigned As[128 * GLD];
    __shared__ unsigned Bs[128 * GLD];

    const int tid  = threadIdx.x;
    const int wid  = tid >> 5, lane = tid & 31;
    const int g    = lane >> 2, t4 = lane & 3;
    const int wm   = wid >> 1,  wn = wid & 1;
    const int bm   = blockIdx.y * 128, bn = blockIdx.x * 128;

    float acc[4][8][4];
#pragma unroll
    for (int i = 0; i < 4; i++)
#pragma unroll
        for (int j = 0; j < 8; j++)
#pragma unroll
            for (int r = 0; r < 4; r++) acc[i][j][r] = 0.f;

    for (int k0 = 0; k0 < K; k0 += 16) {
#pragma unroll
        for (int l = 0; l < 4; l++) {
            int f   = tid + l * 128;          // 0..511
            int row = f >> 2;                 // 0..127
            int c4  = (f & 3) << 2;           // 0,4,8,12
            float4 va = *(const float4*)(A + (size_t)(bm + row) * K + k0 + c4);
            unsigned* ps = &As[row * GLD + c4];
            ps[0] = f2tf(va.x); ps[1] = f2tf(va.y);
            ps[2] = f2tf(va.z); ps[3] = f2tf(va.w);
            float4 vb = *(const float4*)(Bm + (size_t)(bn + row) * K + k0 + c4);
            unsigned* qs = &Bs[row * GLD + c4];
            qs[0] = f2tf(vb.x); qs[1] = f2tf(vb.y);
            qs[2] = f2tf(vb.z); qs[3] = f2tf(vb.w);
        }
        __syncthreads();

#pragma unroll
        for (int ks = 0; ks < 16; ks += 8) {
            unsigned a[4][4], b[8][2];
#pragma unroll
            for (int mt = 0; mt < 4; mt++) {
                int m = wm * 64 + mt * 16;
                a[mt][0] = As[(m + g    ) * GLD + ks + t4];
                a[mt][1] = As[(m + g + 8) * GLD + ks + t4];
                a[mt][2] = As[(m + g    ) * GLD + ks + t4 + 4];
                a[mt][3] = As[(m + g + 8) * GLD + ks + t4 + 4];
            }
#pragma unroll
            for (int nt = 0; nt < 8; nt++) {
                int n = wn * 64 + nt * 8;
                b[nt][0] = Bs[(n + g) * GLD + ks + t4];
                b[nt][1] = Bs[(n + g) * GLD + ks + t4 + 4];
            }
#pragma unroll
            for (int mt = 0; mt < 4; mt++)
#pragma unroll
                for (int nt = 0; nt < 8; nt++)
                    mma_tf32(acc[mt][nt], a[mt], b[nt]);
        }
        __syncthreads();
    }

#pragma unroll
    for (int mt = 0; mt < 4; mt++) {
        int r0 = bm + wm * 64 + mt * 16 + g;
#pragma unroll
        for (int nt = 0; nt < 8; nt++) {
            int c = bn + wn * 64 + nt * 8 + 2 * t4;
            *(float2*)(Cm + (size_t)r0 * N + c) =
                make_float2(acc[mt][nt][0], acc[mt][nt][1]);
            *(float2*)(Cm + (size_t)(r0 + 8) * N + c) =
                make_float2(acc[mt][nt][2], acc[mt][nt][3]);
        }
    }
}

// ---------------- RoPE (NeoX rotate-half), in place -------------------------
__global__ void rope_kernel(float* __restrict__ p, const float* __restrict__ freqs, int nh)
{
    int idx = blockIdx.x * blockDim.x + threadIdx.x;
    int pr = idx & 63;
    int h  = (idx >> 6) % nh;
    int bt = idx / (64 * nh);
    int t  = bt & (Tc - 1);
    float c = freqs[(t * 64 + pr) * 2 + 0];
    float s = freqs[(t * 64 + pr) * 2 + 1];
    float* base = p + ((size_t)bt * nh + h) * Dc;
    float u0 = base[pr], u1 = base[pr + 64];
    base[pr]      = u0 * c - u1 * s;
    base[pr + 64] = u1 * c + u0 * s;
}

// ---------------- flash attention, tf32 mma, causal GQA ---------------------
// 64 q-rows per block, 64-col KV tiles, 256 threads (8 warps).
// smem pitches chosen so fragment bank maps are permutations mod 32.
#define QLD 132   // Q/K (row-major [r][d]) pitch
#define VLD 136   // V (row-major [j][d]) pitch
#define SLD 76    // S/P pitch
#define ATT_SMEM_WORDS (64*QLD*2 + 64*VLD + 64*SLD + 128)
#define ATT_SMEM_BYTES (ATT_SMEM_WORDS * 4)

__global__ void __launch_bounds__(256, 1)
attn_kernel(const float* __restrict__ q, const float* __restrict__ k,
            const float* __restrict__ v, float* __restrict__ o)
{
    extern __shared__ char smraw[];
    unsigned* Qsu  = (unsigned*)smraw;          // [64][132] tf32
    unsigned* Ksu  = Qsu + 64 * QLD;            // [64][132] tf32
    unsigned* Vsu  = Ksu + 64 * QLD;            // [64][136] tf32
    float*    Ss   = (float*)(Vsu + 64 * VLD);  // [64][76]  fp32 S / tf32 P
    unsigned* Ssu  = (unsigned*)Ss;
    float*    row_f = Ss + 64 * SLD;            // [64]
    float*    row_l = row_f + 64;               // [64]

    const int qt = blockIdx.x, h = blockIdx.y, b = blockIdx.z;
    const int kvh = h >> 2;
    const int tid = threadIdx.x;
    const int wid = tid >> 5, lane = tid & 31;
    const int g   = lane >> 2, t4 = lane & 3;
    const int lr  = lane >> 4, lc = lane & 15;
    // phase A warp grid: 2 (rows of 32) x 4 (cols of 16)
    const int wmA = wid >> 2, wnA = wid & 3;
    // phase C warp grid: 2 (rows of 32) x 4 (cols of 32)
    const int wmC = wid >> 2, wnC = wid & 3;
    // softmax assignment: 4 threads per row, stride-4 columns
    const int sr = tid >> 2, sq = tid & 3;
    const float qscale = 0.08838834764831845f;  // 1/sqrt(128)

    // ---- load Q tile (row-major [r][d], tf32, pre-scaled) ----
#pragma unroll
    for (int it = 0; it < 4; it++) {
        int r = it * 16 + wid * 2 + lr;
        int t = qt * 64 + r;
        const float* gq = q + (((size_t)(b * Tc + t)) * Hc + h) * Dc;
#pragma unroll
        for (int dit = 0; dit < 2; dit++) {
            int d = lc * 4 + dit * 64;
            float4 val = *(const float4*)(gq + d);
            uint4 u;
            u.x = f2tf(val.x * qscale); u.y = f2tf(val.y * qscale);
            u.z = f2tf(val.z * qscale); u.w = f2tf(val.w * qscale);
            *(uint4*)&Qsu[r * QLD + d] = u;
        }
    }

    float accO[2][4][4];
#pragma unroll
    for (int i = 0; i < 2; i++)
#pragma unroll
        for (int j = 0; j < 4; j++)
#pragma unroll
            for (int r = 0; r < 4; r++) accO[i][j][r] = 0.f;

    float m_r = -1e30f, l_r = 0.f;  // per-row stats (quad-redundant)

    for (int kt = 0; kt <= qt; kt++) {
        // ---- load K ([c][d]) and V ([j][d]) tiles as tf32 ----
#pragma unroll
        for (int it = 0; it < 4; it++) {
            int c0 = it * 16 + wid * 2 + lr;
            int t  = kt * 64 + c0;
            const float* gk = k + (((size_t)(b * Tc + t)) * HKVc + kvh) * Dc;
            const float* gv = v + (((size_t)(b * Tc + t)) * HKVc + kvh) * Dc;
#pragma unroll
            for (int dit = 0; dit < 2; dit++) {
                int d = lc * 4 + dit * 64;
                float4 kv = *(const float4*)(gk + d);
                uint4 uk;
                uk.x = f2tf(kv.x); uk.y = f2tf(kv.y);
                uk.z = f2tf(kv.z); uk.w = f2tf(kv.w);
                *(uint4*)&Ksu[c0 * QLD + d] = uk;
                float4 vv = *(const float4*)(gv + d);
                uint4 uv;
                uv.x = f2tf(vv.x); uv.y = f2tf(vv.y);
                uv.z = f2tf(vv.z); uv.w = f2tf(vv.w);
                *(uint4*)&Vsu[c0 * VLD + d] = uv;
            }
        }
        __syncthreads();

        // ---- phase A: S(64x64) = Q K^T, warp tile 32x16 ----
        {
            float accS[2][2][4];
#pragma unroll
            for (int i = 0; i < 2; i++)
#pragma unroll
                for (int j = 0; j < 2; j++)
#pragma unroll
                    for (int r = 0; r < 4; r++) accS[i][j][r] = 0.f;

#pragma unroll
            for (int ks = 0; ks < 128; ks += 8) {
                unsigned a[2][4], bb[2][2];
#pragma unroll
                for (int mt = 0; mt < 2; mt++) {
                    int m = wmA * 32 + mt * 16;
                    a[mt][0] = Qsu[(m + g    ) * QLD + ks + t4];
                    a[mt][1] = Qsu[(m + g + 8) * QLD + ks + t4];
                    a[mt][2] = Qsu[(m + g    ) * QLD + ks + t4 + 4];
                    a[mt][3] = Qsu[(m + g + 8) * QLD + ks + t4 + 4];
                }
#pragma unroll
                for (int nt = 0; nt < 2; nt++) {
                    int n = wnA * 16 + nt * 8;
                    bb[nt][0] = Ksu[(n + g) * QLD + ks + t4];
                    bb[nt][1] = Ksu[(n + g) * QLD + ks + t4 + 4];
                }
#pragma unroll
                for (int mt = 0; mt < 2; mt++)
#pragma unroll
                    for (int nt = 0; nt < 2; nt++)
                        mma_tf32(accS[mt][nt], a[mt], bb[nt]);
            }
#pragma unroll
            for (int mt = 0; mt < 2; mt++) {
                int r0 = wmA * 32 + mt * 16 + g;
#pragma unroll
                for (int nt = 0; nt < 2; nt++) {
                    int c0 = wnA * 16 + nt * 8 + 2 * t4;
                    *(float2*)&Ss[r0 * SLD + c0] =
                        make_float2(accS[mt][nt][0], accS[mt][nt][1]);
                    *(float2*)&Ss[(r0 + 8) * SLD + c0] =
                        make_float2(accS[mt][nt][2], accS[mt][nt][3]);
                }
            }
        }
        __syncthreads();

        // ---- phase B: online softmax, 4 threads per row ----
        {
            const bool diag = (kt == qt);
            float sv[16];
            float mnew = m_r;
#pragma unroll
            for (int jj = 0; jj < 16; jj++) {
                int c = sq + 4 * jj;
                float s = Ss[sr * SLD + c];
                if (diag && c > sr) s = -1e30f;
                sv[jj] = s;
                mnew = fmaxf(mnew, s);
            }
            mnew = fmaxf(mnew, __shfl_xor_sync(0xffffffffu, mnew, 1));
            mnew = fmaxf(mnew, __shfl_xor_sync(0xffffffffu, mnew, 2));
            float f = __expf(m_r - mnew);
            float ssum = 0.f;
#pragma unroll
            for (int jj = 0; jj < 16; jj++) {
                float e = __expf(sv[jj] - mnew);
                ssum += e;
                Ssu[sr * SLD + sq + 4 * jj] = f2tf(e);
            }
            ssum += __shfl_xor_sync(0xffffffffu, ssum, 1);
            ssum += __shfl_xor_sync(0xffffffffu, ssum, 2);
            l_r = l_r * f + ssum;
            m_r = mnew;
            if (sq == 0) { row_f[sr] = f; row_l[sr] = l_r; }
        }
        __syncthreads();

        // ---- phase C: O(64x128) = O*f + P V, warp tile 32x32 ----
        {
#pragma unroll
            for (int mt = 0; mt < 2; mt++) {
                int r0 = wmC * 32 + mt * 16 + g;
                float f0 = row_f[r0], f1 = row_f[r0 + 8];
#pragma unroll
                for (int nt = 0; nt < 4; nt++) {
                    accO[mt][nt][0] *= f0; accO[mt][nt][1] *= f0;
                    accO[mt][nt][2] *= f1; accO[mt][nt][3] *= f1;
                }
            }
#pragma unroll
            for (int ks = 0; ks < 64; ks += 8) {
                unsigned a[2][4], bb[4][2];
#pragma unroll
                for (int mt = 0; mt < 2; mt++) {
                    int m = wmC * 32 + mt * 16;
                    a[mt][0] = Ssu[(m + g    ) * SLD + ks + t4];
                    a[mt][1] = Ssu[(m + g + 8) * SLD + ks + t4];
                    a[mt][2] = Ssu[(m + g    ) * SLD + ks + t4 + 4];
                    a[mt][3] = Ssu[(m + g + 8) * SLD + ks + t4 + 4];
                }
#pragma unroll
                for (int nt = 0; nt < 4; nt++) {
                    int n = wnC * 32 + nt * 8;
                    bb[nt][0] = Vsu[(ks + t4    ) * VLD + n + g];
                    bb[nt][1] = Vsu[(ks + t4 + 4) * VLD + n + g];
                }
#pragma unroll
                for (int mt = 0; mt < 2; mt++)
#pragma unroll
                    for (int nt = 0; nt < 4; nt++)
                        mma_tf32(accO[mt][nt], a[mt], bb[nt]);
            }
        }
        __syncthreads();
    }

    // ---- epilogue: normalize and store ----
#pragma unroll
    for (int mt = 0; mt < 2; mt++) {
        int r0 = wmC * 32 + mt * 16 + g;
        float l0 = 1.f / row_l[r0], l1 = 1.f / row_l[r0 + 8];
        int t0 = qt * 64 + r0;
        float* go0 = o + (((size_t)(b * Tc + t0)) * Hc + h) * Dc;
        float* go1 = o + (((size_t)(b * Tc + t0 + 8)) * Hc + h) * Dc;
#pragma unroll
        for (int nt = 0; nt < 4; nt++) {
            int c = wnC * 32 + nt * 8 + 2 * t4;
            *(float2*)(go0 + c) = make_float2(accO[mt][nt][0] * l0,
                                              accO[mt][nt][1] * l0);
            *(float2*)(go1 + c) = make_float2(accO[mt][nt][2] * l1,
                                              accO[mt][nt][3] * l1);
        }
    }
}

// ---------------- host launcher ---------------------------------------------
extern "C" void kernel_launch(void* const* d_in, const int* in_sizes, int n_in,
                              void* d_out, int out_size)
{
    (void)in_sizes; (void)n_in; (void)out_size;
    const float* x     = (const float*)d_in[0];
    const float* freqs = (const float*)d_in[1];
    const float* Wq    = (const float*)d_in[2];
    const float* Wk    = (const float*)d_in[3];
    const float* Wv    = (const float*)d_in[4];
    const float* Wo    = (const float*)d_in[5];
    float* out = (float*)d_out;

    float *q, *k, *v, *ao;
    cudaGetSymbolAddress((void**)&q,  g_q);
    cudaGetSymbolAddress((void**)&k,  g_k);
    cudaGetSymbolAddress((void**)&v,  g_v);
    cudaGetSymbolAddress((void**)&ao, g_ao);

    cudaFuncSetAttribute(attn_kernel,
                         cudaFuncAttributeMaxDynamicSharedMemorySize,
                         ATT_SMEM_BYTES);

    // projections: q = x@Wq^T, k = x@Wk^T, v = x@Wv^T (tf32 tensor cores)
    gemm_tf32_nt<<<dim3(Cc  / 128, Mrows / 128), 128>>>(x, Wq, q,  Cc,  Cc);
    gemm_tf32_nt<<<dim3(KVC / 128, Mrows / 128), 128>>>(x, Wk, k,  KVC, Cc);
    gemm_tf32_nt<<<dim3(KVC / 128, Mrows / 128), 128>>>(x, Wv, v,  KVC, Cc);

    // RoPE (in place, fp32)
    rope_kernel<<<(Mrows * Hc   * 64) / 256, 256>>>(q, freqs, Hc);
    rope_kernel<<<(Mrows * HKVc * 64) / 256, 256>>>(k, freqs, HKVc);

    // causal GQA flash attention (tf32 tensor cores)
    attn_kernel<<<dim3(Tc / 64, Hc, Bc), 256, ATT_SMEM_BYTES>>>(q, k, v, ao);

    // output projection: out = ao @ Wo^T
    gemm_tf32_nt<<<dim3(Cc / 128, Mrows / 128), 128>>>(ao, Wo, out, Cc, Cc);
}

// round 6
// speedup vs baseline: 2.9496x; 1.0026x over previous
#include <cuda_runtime.h>
#include <math.h>

#define Bc   4
#define Tc   2048
#define Cc   2048
#define Hc   16
#define HKVc 4
#define Dc   128
#define Mrows (Bc*Tc)          // 8192
#define KVC  (HKVc*Dc)         // 512

// ---------------- scratch (device globals; no runtime allocation) -----------
__device__ float g_q [(size_t)Mrows*Cc];   // [b,t,h,d]
__device__ float g_k [(size_t)Mrows*KVC];  // [b,t,hkv,d]
__device__ float g_v [(size_t)Mrows*KVC];
__device__ float g_ao[(size_t)Mrows*Cc];   // attention output [b,t,h,d]

// ---------------- tf32 helpers ----------------------------------------------
__device__ __forceinline__ unsigned f2tf(float x) {
    unsigned u;
    asm("cvt.rna.tf32.f32 %0, %1;" : "=r"(u) : "f"(x));
    return u;
}

// D = A(16x8, row) * B(8x8, col) + D, tf32 in, fp32 out
__device__ __forceinline__ void mma_tf32(float* d, const unsigned* a, const unsigned* b) {
    asm volatile(
        "mma.sync.aligned.m16n8k8.row.col.f32.tf32.tf32.f32 "
        "{%0,%1,%2,%3},{%4,%5,%6,%7},{%8,%9},{%0,%1,%2,%3};"
        : "+f"(d[0]), "+f"(d[1]), "+f"(d[2]), "+f"(d[3])
        : "r"(a[0]), "r"(a[1]), "r"(a[2]), "r"(a[3]), "r"(b[0]), "r"(b[1]));
}

// ---------------- tf32 GEMM, C[m,n] = sum_k A[m,k]*B[n,k] (NT) ---------------
// 128x128 block tile, BK=16, 128 threads (4 warps, 2x2 grid of 64x64 warp tiles)
#define GLD 20   // smem row pitch (floats): conflict-free for frag loads + STS

__global__ void __launch_bounds__(128, 2)
gemm_tf32_nt(const float* __restrict__ A, const float* __restrict__ Bm,
             float* __restrict__ Cm, int N, int K)
{
    __shared__ unsigned As[128 * GLD];
    __shared__ unsigned Bs[128 * GLD];

    const int tid  = threadIdx.x;
    const int wid  = tid >> 5, lane = tid & 31;
    const int g    = lane >> 2, t4 = lane & 3;
    const int wm   = wid >> 1,  wn = wid & 1;
    const int bm   = blockIdx.y * 128, bn = blockIdx.x * 128;

    float acc[4][8][4];
#pragma unroll
    for (int i = 0; i < 4; i++)
#pragma unroll
        for (int j = 0; j < 8; j++)
#pragma unroll
            for (int r = 0; r < 4; r++) acc[i][j][r] = 0.f;

    for (int k0 = 0; k0 < K; k0 += 16) {
#pragma unroll
        for (int l = 0; l < 4; l++) {
            int f   = tid + l * 128;          // 0..511
            int row = f >> 2;                 // 0..127
            int c4  = (f & 3) << 2;           // 0,4,8,12
            float4 va = *(const float4*)(A + (size_t)(bm + row) * K + k0 + c4);
            unsigned* ps = &As[row * GLD + c4];
            ps[0] = f2tf(va.x); ps[1] = f2tf(va.y);
            ps[2] = f2tf(va.z); ps[3] = f2tf(va.w);
            float4 vb = *(const float4*)(Bm + (size_t)(bn + row) * K + k0 + c4);
            unsigned* qs = &Bs[row * GLD + c4];
            qs[0] = f2tf(vb.x); qs[1] = f2tf(vb.y);
            qs[2] = f2tf(vb.z); qs[3] = f2tf(vb.w);
        }
        __syncthreads();

#pragma unroll
        for (int ks = 0; ks < 16; ks += 8) {
            unsigned a[4][4], b[8][2];
#pragma unroll
            for (int mt = 0; mt < 4; mt++) {
                int m = wm * 64 + mt * 16;
                a[mt][0] = As[(m + g    ) * GLD + ks + t4];
                a[mt][1] = As[(m + g + 8) * GLD + ks + t4];
                a[mt][2] = As[(m + g    ) * GLD + ks + t4 + 4];
                a[mt][3] = As[(m + g + 8) * GLD + ks + t4 + 4];
            }
#pragma unroll
            for (int nt = 0; nt < 8; nt++) {
                int n = wn * 64 + nt * 8;
                b[nt][0] = Bs[(n + g) * GLD + ks + t4];
                b[nt][1] = Bs[(n + g) * GLD + ks + t4 + 4];
            }
#pragma unroll
            for (int mt = 0; mt < 4; mt++)
#pragma unroll
                for (int nt = 0; nt < 8; nt++)
                    mma_tf32(acc[mt][nt], a[mt], b[nt]);
        }
        __syncthreads();
    }

#pragma unroll
    for (int mt = 0; mt < 4; mt++) {
        int r0 = bm + wm * 64 + mt * 16 + g;
#pragma unroll
        for (int nt = 0; nt < 8; nt++) {
            int c = bn + wn * 64 + nt * 8 + 2 * t4;
            *(float2*)(Cm + (size_t)r0 * N + c) =
                make_float2(acc[mt][nt][0], acc[mt][nt][1]);
            *(float2*)(Cm + (size_t)(r0 + 8) * N + c) =
                make_float2(acc[mt][nt][2], acc[mt][nt][3]);
        }
    }
}

// ---------------- RoPE (NeoX rotate-half), in place -------------------------
__global__ void rope_kernel(float* __restrict__ p, const float* __restrict__ freqs, int nh)
{
    int idx = blockIdx.x * blockDim.x + threadIdx.x;
    int pr = idx & 63;
    int h  = (idx >> 6) % nh;
    int bt = idx / (64 * nh);
    int t  = bt & (Tc - 1);
    float c = freqs[(t * 64 + pr) * 2 + 0];
    float s = freqs[(t * 64 + pr) * 2 + 1];
    float* base = p + ((size_t)bt * nh + h) * Dc;
    float u0 = base[pr], u1 = base[pr + 64];
    base[pr]      = u0 * c - u1 * s;
    base[pr + 64] = u1 * c + u0 * s;
}

// ---------------- flash attention, tf32 mma, causal GQA ---------------------
// 64 q-rows per block, 64-col KV tiles, 256 threads (8 warps).
// smem pitches chosen so fragment bank maps are permutations mod 32.
#define QLD 132   // Q/K (row-major [r][d]) pitch
#define VLD 136   // V (row-major [j][d]) pitch
#define SLD 76    // S/P pitch
#define ATT_SMEM_WORDS (64*QLD*2 + 64*VLD + 64*SLD + 128)
#define ATT_SMEM_BYTES (ATT_SMEM_WORDS * 4)

__global__ void __launch_bounds__(256, 1)
attn_kernel(const float* __restrict__ q, const float* __restrict__ k,
            const float* __restrict__ v, float* __restrict__ o)
{
    extern __shared__ char smraw[];
    unsigned* Qsu  = (unsigned*)smraw;          // [64][132] tf32
    unsigned* Ksu  = Qsu + 64 * QLD;            // [64][132] tf32
    unsigned* Vsu  = Ksu + 64 * QLD;            // [64][136] tf32
    float*    Ss   = (float*)(Vsu + 64 * VLD);  // [64][76]  fp32 S / tf32 P
    unsigned* Ssu  = (unsigned*)Ss;
    float*    row_f = Ss + 64 * SLD;            // [64]
    float*    row_l = row_f + 64;               // [64]

    const int qt = blockIdx.x, h = blockIdx.y, b = blockIdx.z;
    const int kvh = h >> 2;
    const int tid = threadIdx.x;
    const int wid = tid >> 5, lane = tid & 31;
    const int g   = lane >> 2, t4 = lane & 3;
    const int lr  = lane >> 4, lc = lane & 15;
    // phase A warp grid: 2 (rows of 32) x 4 (cols of 16)
    const int wmA = wid >> 2, wnA = wid & 3;
    // phase C warp grid: 2 (rows of 32) x 4 (cols of 32)
    const int wmC = wid >> 2, wnC = wid & 3;
    // softmax assignment: 4 threads per row, stride-4 columns
    const int sr = tid >> 2, sq = tid & 3;
    const float qscale = 0.08838834764831845f;  // 1/sqrt(128)

    // ---- load Q tile (row-major [r][d], tf32, pre-scaled) ----
#pragma unroll
    for (int it = 0; it < 4; it++) {
        int r = it * 16 + wid * 2 + lr;
        int t = qt * 64 + r;
        const float* gq = q + (((size_t)(b * Tc + t)) * Hc + h) * Dc;
#pragma unroll
        for (int dit = 0; dit < 2; dit++) {
            int d = lc * 4 + dit * 64;
            float4 val = *(const float4*)(gq + d);
            uint4 u;
            u.x = f2tf(val.x * qscale); u.y = f2tf(val.y * qscale);
            u.z = f2tf(val.z * qscale); u.w = f2tf(val.w * qscale);
            *(uint4*)&Qsu[r * QLD + d] = u;
        }
    }

    float accO[2][4][4];
#pragma unroll
    for (int i = 0; i < 2; i++)
#pragma unroll
        for (int j = 0; j < 4; j++)
#pragma unroll
            for (int r = 0; r < 4; r++) accO[i][j][r] = 0.f;

    float m_r = -1e30f, l_r = 0.f;  // per-row stats (quad-redundant)

    for (int kt = 0; kt <= qt; kt++) {
        // ---- load K ([c][d]) and V ([j][d]) tiles as tf32 ----
#pragma unroll
        for (int it = 0; it < 4; it++) {
            int c0 = it * 16 + wid * 2 + lr;
            int t  = kt * 64 + c0;
            const float* gk = k + (((size_t)(b * Tc + t)) * HKVc + kvh) * Dc;
            const float* gv = v + (((size_t)(b * Tc + t)) * HKVc + kvh) * Dc;
#pragma unroll
            for (int dit = 0; dit < 2; dit++) {
                int d = lc * 4 + dit * 64;
                float4 kv = *(const float4*)(gk + d);
                uint4 uk;
                uk.x = f2tf(kv.x); uk.y = f2tf(kv.y);
                uk.z = f2tf(kv.z); uk.w = f2tf(kv.w);
                *(uint4*)&Ksu[c0 * QLD + d] = uk;
                float4 vv = *(const float4*)(gv + d);
                uint4 uv;
                uv.x = f2tf(vv.x); uv.y = f2tf(vv.y);
                uv.z = f2tf(vv.z); uv.w = f2tf(vv.w);
                *(uint4*)&Vsu[c0 * VLD + d] = uv;
            }
        }
        __syncthreads();

        // ---- phase A: S(64x64) = Q K^T, warp tile 32x16 ----
        {
            float accS[2][2][4];
#pragma unroll
            for (int i = 0; i < 2; i++)
#pragma unroll
                for (int j = 0; j < 2; j++)
#pragma unroll
                    for (int r = 0; r < 4; r++) accS[i][j][r] = 0.f;

#pragma unroll
            for (int ks = 0; ks < 128; ks += 8) {
                unsigned a[2][4], bb[2][2];
#pragma unroll
                for (int mt = 0; mt < 2; mt++) {
                    int m = wmA * 32 + mt * 16;
                    a[mt][0] = Qsu[(m + g    ) * QLD + ks + t4];
                    a[mt][1] = Qsu[(m + g + 8) * QLD + ks + t4];
                    a[mt][2] = Qsu[(m + g    ) * QLD + ks + t4 + 4];
                    a[mt][3] = Qsu[(m + g + 8) * QLD + ks + t4 + 4];
                }
#pragma unroll
                for (int nt = 0; nt < 2; nt++) {
                    int n = wnA * 16 + nt * 8;
                    bb[nt][0] = Ksu[(n + g) * QLD + ks + t4];
                    bb[nt][1] = Ksu[(n + g) * QLD + ks + t4 + 4];
                }
#pragma unroll
                for (int mt = 0; mt < 2; mt++)
#pragma unroll
                    for (int nt = 0; nt < 2; nt++)
                        mma_tf32(accS[mt][nt], a[mt], bb[nt]);
            }
#pragma unroll
            for (int mt = 0; mt < 2; mt++) {
                int r0 = wmA * 32 + mt * 16 + g;
#pragma unroll
                for (int nt = 0; nt < 2; nt++) {
                    int c0 = wnA * 16 + nt * 8 + 2 * t4;
                    *(float2*)&Ss[r0 * SLD + c0] =
                        make_float2(accS[mt][nt][0], accS[mt][nt][1]);
                    *(float2*)&Ss[(r0 + 8) * SLD + c0] =
                        make_float2(accS[mt][nt][2], accS[mt][nt][3]);
                }
            }
        }
        __syncthreads();

        // ---- phase B: online softmax, 4 threads per row ----
        {
            const bool diag = (kt == qt);
            float sv[16];
            float mnew = m_r;
#pragma unroll
            for (int jj = 0; jj < 16; jj++) {
                int c = sq + 4 * jj;
                float s = Ss[sr * SLD + c];
                if (diag && c > sr) s = -1e30f;
                sv[jj] = s;
                mnew = fmaxf(mnew, s);
            }
            mnew = fmaxf(mnew, __shfl_xor_sync(0xffffffffu, mnew, 1));
            mnew = fmaxf(mnew, __shfl_xor_sync(0xffffffffu, mnew, 2));
            float f = __expf(m_r - mnew);
            float ssum = 0.f;
#pragma unroll
            for (int jj = 0; jj < 16; jj++) {
                float e = __expf(sv[jj] - mnew);
                ssum += e;
                Ssu[sr * SLD + sq + 4 * jj] = f2tf(e);
            }
            ssum += __shfl_xor_sync(0xffffffffu, ssum, 1);
            ssum += __shfl_xor_sync(0xffffffffu, ssum, 2);
            l_r = l_r * f + ssum;
            m_r = mnew;
            if (sq == 0) { row_f[sr] = f; row_l[sr] = l_r; }
        }
        __syncthreads();

        // ---- phase C: O(64x128) = O*f + P V, warp tile 32x32 ----
        {
#pragma unroll
            for (int mt = 0; mt < 2; mt++) {
                int r0 = wmC * 32 + mt * 16 + g;
                float f0 = row_f[r0], f1 = row_f[r0 + 8];
#pragma unroll
                for (int nt = 0; nt < 4; nt++) {
                    accO[mt][nt][0] *= f0; accO[mt][nt][1] *= f0;
                    accO[mt][nt][2] *= f1; accO[mt][nt][3] *= f1;
                }
            }
#pragma unroll
            for (int ks = 0; ks < 64; ks += 8) {
                unsigned a[2][4], bb[4][2];
#pragma unroll
                for (int mt = 0; mt < 2; mt++) {
                    int m = wmC * 32 + mt * 16;
                    a[mt][0] = Ssu[(m + g    ) * SLD + ks + t4];
                    a[mt][1] = Ssu[(m + g + 8) * SLD + ks + t4];
                    a[mt][2] = Ssu[(m + g    ) * SLD + ks + t4 + 4];
                    a[mt][3] = Ssu[(m + g + 8) * SLD + ks + t4 + 4];
                }
#pragma unroll
                for (int nt = 0; nt < 4; nt++) {
                    int n = wnC * 32 + nt * 8;
                    bb[nt][0] = Vsu[(ks + t4    ) * VLD + n + g];
                    bb[nt][1] = Vsu[(ks + t4 + 4) * VLD + n + g];
                }
#pragma unroll
                for (int mt = 0; mt < 2; mt++)
#pragma unroll
                    for (int nt = 0; nt < 4; nt++)
                        mma_tf32(accO[mt][nt], a[mt], bb[nt]);
            }
        }
        __syncthreads();
    }

    // ---- epilogue: normalize and store ----
#pragma unroll
    for (int mt = 0; mt < 2; mt++) {
        int r0 = wmC * 32 + mt * 16 + g;
        float l0 = 1.f / row_l[r0], l1 = 1.f / row_l[r0 + 8];
        int t0 = qt * 64 + r0;
        float* go0 = o + (((size_t)(b * Tc + t0)) * Hc + h) * Dc;
        float* go1 = o + (((size_t)(b * Tc + t0 + 8)) * Hc + h) * Dc;
#pragma unroll
        for (int nt = 0; nt < 4; nt++) {
            int c = wnC * 32 + nt * 8 + 2 * t4;
            *(float2*)(go0 + c) = make_float2(accO[mt][nt][0] * l0,
                                              accO[mt][nt][1] * l0);
            *(float2*)(go1 + c) = make_float2(accO[mt][nt][2] * l1,
                                              accO[mt][nt][3] * l1);
        }
    }
}

// ---------------- host launcher ---------------------------------------------
extern "C" void kernel_launch(void* const* d_in, const int* in_sizes, int n_in,
                              void* d_out, int out_size)
{
    (void)in_sizes; (void)n_in; (void)out_size;
    const float* x     = (const float*)d_in[0];
    const float* freqs = (const float*)d_in[1];
    const float* Wq    = (const float*)d_in[2];
    const float* Wk    = (const float*)d_in[3];
    const float* Wv    = (const float*)d_in[4];
    const float* Wo    = (const float*)d_in[5];
    float* out = (float*)d_out;

    float *q, *k, *v, *ao;
    cudaGetSymbolAddress((void**)&q,  g_q);
    cudaGetSymbolAddress((void**)&k,  g_k);
    cudaGetSymbolAddress((void**)&v,  g_v);
    cudaGetSymbolAddress((void**)&ao, g_ao);

    cudaFuncSetAttribute(attn_kernel,
                         cudaFuncAttributeMaxDynamicSharedMemorySize,
                         ATT_SMEM_BYTES);

    // projections: q = x@Wq^T, k = x@Wk^T, v = x@Wv^T (tf32 tensor cores)
    gemm_tf32_nt<<<dim3(Cc  / 128, Mrows / 128), 128>>>(x, Wq, q,  Cc,  Cc);
    gemm_tf32_nt<<<dim3(KVC / 128, Mrows / 128), 128>>>(x, Wk, k,  KVC, Cc);
    gemm_tf32_nt<<<dim3(KVC / 128, Mrows / 128), 128>>>(x, Wv, v,  KVC, Cc);

    // RoPE (in place, fp32)
    rope_kernel<<<(Mrows * Hc   * 64) / 256, 256>>>(q, freqs, Hc);
    rope_kernel<<<(Mrows * HKVc * 64) / 256, 256>>>(k, freqs, HKVc);

    // causal GQA flash attention (tf32 tensor cores)
    attn_kernel<<<dim3(Tc / 64, Hc, Bc), 256, ATT_SMEM_BYTES>>>(q, k, v, ao);

    // output projection: out = ao @ Wo^T
    gemm_tf32_nt<<<dim3(Cc / 128, Mrows / 128), 128>>>(ao, Wo, out, Cc, Cc);
}

// round 7
// speedup vs baseline: 3.6781x; 1.2470x over previous
#include <cuda_runtime.h>
#include <math.h>

#define Bc   4
#define Tc   2048
#define Cc   2048
#define Hc   16
#define HKVc 4
#define Dc   128
#define Mrows (Bc*Tc)          // 8192
#define KVC  (HKVc*Dc)         // 512

// ---------------- scratch (device globals; no runtime allocation) -----------
__device__ float g_q [(size_t)Mrows*Cc];   // [b,t,h,d]
__device__ float g_k [(size_t)Mrows*KVC];  // [b,t,hkv,d]
__device__ float g_v [(size_t)Mrows*KVC];
__device__ float g_ao[(size_t)Mrows*Cc];   // attention output [b,t,h,d]

// ---------------- tf32 helpers ----------------------------------------------
__device__ __forceinline__ unsigned f2tf(float x) {
    unsigned u;
    asm("cvt.rna.tf32.f32 %0, %1;" : "=r"(u) : "f"(x));
    return u;
}

// D = A(16x8, row) * B(8x8, col) + D, tf32 in, fp32 out
__device__ __forceinline__ void mma_tf32(float* d, const unsigned* a, const unsigned* b) {
    asm volatile(
        "mma.sync.aligned.m16n8k8.row.col.f32.tf32.tf32.f32 "
        "{%0,%1,%2,%3},{%4,%5,%6,%7},{%8,%9},{%0,%1,%2,%3};"
        : "+f"(d[0]), "+f"(d[1]), "+f"(d[2]), "+f"(d[3])
        : "r"(a[0]), "r"(a[1]), "r"(a[2]), "r"(a[3]), "r"(b[0]), "r"(b[1]));
}

// ---------------- tf32 GEMM, C[m,n] = sum_k A[m,k]*B[n,k] (NT) ---------------
// 128x128 block tile, BK=16, 128 threads (4 warps, 2x2 grid of 64x64 warp
// tiles), double-buffered smem + register prefetch.
#define GLD 20   // smem row pitch (uints): conflict-free for frag loads + STS

__global__ void __launch_bounds__(128, 2)
gemm_tf32_nt(const float* __restrict__ A, const float* __restrict__ Bm,
             float* __restrict__ Cm, int N, int K)
{
    __shared__ unsigned As[2][128 * GLD];
    __shared__ unsigned Bs[2][128 * GLD];

    const int tid  = threadIdx.x;
    const int wid  = tid >> 5, lane = tid & 31;
    const int g    = lane >> 2, t4 = lane & 3;
    const int wm   = wid >> 1,  wn = wid & 1;
    const int bm   = blockIdx.y * 128, bn = blockIdx.x * 128;

    float acc[4][8][4];
#pragma unroll
    for (int i = 0; i < 4; i++)
#pragma unroll
        for (int j = 0; j < 8; j++)
#pragma unroll
            for (int r = 0; r < 4; r++) acc[i][j][r] = 0.f;

    float4 va[4], vb[4];

    // prologue: load k0=0 tile
#pragma unroll
    for (int l = 0; l < 4; l++) {
        int f = tid + l * 128, row = f >> 2, c4 = (f & 3) << 2;
        va[l] = *(const float4*)(A  + (size_t)(bm + row) * K + c4);
        vb[l] = *(const float4*)(Bm + (size_t)(bn + row) * K + c4);
    }
#pragma unroll
    for (int l = 0; l < 4; l++) {
        int f = tid + l * 128, row = f >> 2, c4 = (f & 3) << 2;
        unsigned* ps = &As[0][row * GLD + c4];
        ps[0] = f2tf(va[l].x); ps[1] = f2tf(va[l].y);
        ps[2] = f2tf(va[l].z); ps[3] = f2tf(va[l].w);
        unsigned* qs = &Bs[0][row * GLD + c4];
        qs[0] = f2tf(vb[l].x); qs[1] = f2tf(vb[l].y);
        qs[2] = f2tf(vb[l].z); qs[3] = f2tf(vb[l].w);
    }
    __syncthreads();

    int buf = 0;
    for (int k0 = 0; k0 < K; k0 += 16) {
        const bool has_next = (k0 + 16) < K;
        if (has_next) {
#pragma unroll
            for (int l = 0; l < 4; l++) {
                int f = tid + l * 128, row = f >> 2, c4 = (f & 3) << 2;
                va[l] = *(const float4*)(A  + (size_t)(bm + row) * K + k0 + 16 + c4);
                vb[l] = *(const float4*)(Bm + (size_t)(bn + row) * K + k0 + 16 + c4);
            }
        }

#pragma unroll
        for (int ks = 0; ks < 16; ks += 8) {
            unsigned a[4][4], b[8][2];
#pragma unroll
            for (int mt = 0; mt < 4; mt++) {
                int m = wm * 64 + mt * 16;
                a[mt][0] = As[buf][(m + g    ) * GLD + ks + t4];
                a[mt][1] = As[buf][(m + g + 8) * GLD + ks + t4];
                a[mt][2] = As[buf][(m + g    ) * GLD + ks + t4 + 4];
                a[mt][3] = As[buf][(m + g + 8) * GLD + ks + t4 + 4];
            }
#pragma unroll
            for (int nt = 0; nt < 8; nt++) {
                int n = wn * 64 + nt * 8;
                b[nt][0] = Bs[buf][(n + g) * GLD + ks + t4];
                b[nt][1] = Bs[buf][(n + g) * GLD + ks + t4 + 4];
            }
#pragma unroll
            for (int mt = 0; mt < 4; mt++)
#pragma unroll
                for (int nt = 0; nt < 8; nt++)
                    mma_tf32(acc[mt][nt], a[mt], b[nt]);
        }

        if (has_next) {
#pragma unroll
            for (int l = 0; l < 4; l++) {
                int f = tid + l * 128, row = f >> 2, c4 = (f & 3) << 2;
                unsigned* ps = &As[buf ^ 1][row * GLD + c4];
                ps[0] = f2tf(va[l].x); ps[1] = f2tf(va[l].y);
                ps[2] = f2tf(va[l].z); ps[3] = f2tf(va[l].w);
                unsigned* qs = &Bs[buf ^ 1][row * GLD + c4];
                qs[0] = f2tf(vb[l].x); qs[1] = f2tf(vb[l].y);
                qs[2] = f2tf(vb[l].z); qs[3] = f2tf(vb[l].w);
            }
        }
        __syncthreads();
        buf ^= 1;
    }

#pragma unroll
    for (int mt = 0; mt < 4; mt++) {
        int r0 = bm + wm * 64 + mt * 16 + g;
#pragma unroll
        for (int nt = 0; nt < 8; nt++) {
            int c = bn + wn * 64 + nt * 8 + 2 * t4;
            *(float2*)(Cm + (size_t)r0 * N + c) =
                make_float2(acc[mt][nt][0], acc[mt][nt][1]);
            *(float2*)(Cm + (size_t)(r0 + 8) * N + c) =
                make_float2(acc[mt][nt][2], acc[mt][nt][3]);
        }
    }
}

// ---------------- RoPE (NeoX rotate-half), in place -------------------------
__global__ void rope_kernel(float* __restrict__ p, const float* __restrict__ freqs, int nh)
{
    int idx = blockIdx.x * blockDim.x + threadIdx.x;
    int pr = idx & 63;
    int h  = (idx >> 6) % nh;
    int bt = idx / (64 * nh);
    int t  = bt & (Tc - 1);
    float c = freqs[(t * 64 + pr) * 2 + 0];
    float s = freqs[(t * 64 + pr) * 2 + 1];
    float* base = p + ((size_t)bt * nh + h) * Dc;
    float u0 = base[pr], u1 = base[pr + 64];
    base[pr]      = u0 * c - u1 * s;
    base[pr + 64] = u1 * c + u0 * s;
}

// ---------------- flash attention, tf32 mma, register-resident --------------
// 128 q-rows per block, 8 warps (16 rows each), 64-row KV tiles.
// Q lives in A-fragment registers across the whole loop; S/P never touch smem:
// softmax in registers (quad shuffles), P C-frag -> A-frag via intra-quad shfl.
#define KLD  132   // K smem pitch: banks (4g+t4) -> permutation
#define VLD2 136   // V smem pitch: banks (8t4+g) -> permutation
#define ATT_SMEM_BYTES ((64*KLD + 64*VLD2) * 4)

__global__ void __launch_bounds__(256, 1)
attn_kernel(const float* __restrict__ q, const float* __restrict__ k,
            const float* __restrict__ v, float* __restrict__ o)
{
    extern __shared__ unsigned smu[];
    unsigned* Ksu = smu;             // [64][132] tf32
    unsigned* Vsu = smu + 64 * KLD;  // [64][136] tf32

    const int qt = blockIdx.x, h = blockIdx.y, b = blockIdx.z;
    const int kvh = h >> 2;
    const int tid = threadIdx.x;
    const int wid = tid >> 5, lane = tid & 31;
    const int g   = lane >> 2, t4 = lane & 3;
    const int t4p = t4 & 1;
    const int srcbase = (lane & ~3) | (t4 >> 1);
    const float qscale = 0.08838834764831845f;  // 1/sqrt(128)

    const int qrow0 = qt * 128 + wid * 16;   // this warp's first q row

    // ---- Q fragments in registers for the whole kernel ----
    unsigned qf[16][4];
    {
        const float* q0 = q + (((size_t)(b * Tc + qrow0 + g    )) * Hc + h) * Dc;
        const float* q1 = q + (((size_t)(b * Tc + qrow0 + g + 8)) * Hc + h) * Dc;
#pragma unroll
        for (int ks = 0; ks < 16; ks++) {
            qf[ks][0] = f2tf(q0[ks * 8 + t4    ] * qscale);
            qf[ks][1] = f2tf(q1[ks * 8 + t4    ] * qscale);
            qf[ks][2] = f2tf(q0[ks * 8 + t4 + 4] * qscale);
            qf[ks][3] = f2tf(q1[ks * 8 + t4 + 4] * qscale);
        }
    }

    float accO[16][4];
#pragma unroll
    for (int nt = 0; nt < 16; nt++)
#pragma unroll
        for (int r = 0; r < 4; r++) accO[nt][r] = 0.f;

    float m0 = -1e30f, m1 = -1e30f, l0 = 0.f, l1 = 0.f;

    const int nkt = 2 * qt + 2;
    for (int kt = 0; kt < nkt; kt++) {
        // ---- cooperative K/V tile load (fp32 -> tf32 -> smem) ----
        {
            const int tbase = kt * 64;
#pragma unroll
            for (int l = 0; l < 8; l++) {
                int f = tid + l * 256;         // 0..2047
                int row = f >> 5;              // 0..63
                int c4  = (f & 31) << 2;       // 0..124
                const float* gk = k + (((size_t)(b * Tc + tbase + row)) * HKVc + kvh) * Dc + c4;
                float4 kv = *(const float4*)gk;
                unsigned* ps = &Ksu[row * KLD + c4];
                ps[0] = f2tf(kv.x); ps[1] = f2tf(kv.y);
                ps[2] = f2tf(kv.z); ps[3] = f2tf(kv.w);
                const float* gv = v + (((size_t)(b * Tc + tbase + row)) * HKVc + kvh) * Dc + c4;
                float4 vv = *(const float4*)gv;
                unsigned* qs = &Vsu[row * VLD2 + c4];
                qs[0] = f2tf(vv.x); qs[1] = f2tf(vv.y);
                qs[2] = f2tf(vv.z); qs[3] = f2tf(vv.w);
            }
        }
        __syncthreads();

        if (kt * 64 <= qrow0 + 15) {   // warp has unmasked work in this tile
            // ---- phase A: S(16x64) = Q K^T, Q from regs ----
            float accS[8][4];
#pragma unroll
            for (int nt = 0; nt < 8; nt++)
#pragma unroll
                for (int r = 0; r < 4; r++) accS[nt][r] = 0.f;

#pragma unroll
            for (int ks = 0; ks < 16; ks++) {
                unsigned bb[8][2];
#pragma unroll
                for (int nt = 0; nt < 8; nt++) {
                    bb[nt][0] = Ksu[(nt * 8 + g) * KLD + ks * 8 + t4];
                    bb[nt][1] = Ksu[(nt * 8 + g) * KLD + ks * 8 + t4 + 4];
                }
#pragma unroll
                for (int nt = 0; nt < 8; nt++)
                    mma_tf32(accS[nt], qf[ks], bb[nt]);
            }

            // ---- causal mask (register) ----
            if (kt * 64 + 63 > qrow0) {
                const int r0 = qrow0 + g, r1 = r0 + 8;
#pragma unroll
                for (int nt = 0; nt < 8; nt++) {
                    int c0 = kt * 64 + nt * 8 + 2 * t4;
                    if (c0     > r0) accS[nt][0] = -1e30f;
                    if (c0 + 1 > r0) accS[nt][1] = -1e30f;
                    if (c0     > r1) accS[nt][2] = -1e30f;
                    if (c0 + 1 > r1) accS[nt][3] = -1e30f;
                }
            }

            // ---- register online softmax (quad = one row pair) ----
            float mt0 = -1e30f, mt1 = -1e30f;
#pragma unroll
            for (int nt = 0; nt < 8; nt++) {
                mt0 = fmaxf(mt0, fmaxf(accS[nt][0], accS[nt][1]));
                mt1 = fmaxf(mt1, fmaxf(accS[nt][2], accS[nt][3]));
            }
            mt0 = fmaxf(mt0, __shfl_xor_sync(0xffffffffu, mt0, 1));
            mt0 = fmaxf(mt0, __shfl_xor_sync(0xffffffffu, mt0, 2));
            mt1 = fmaxf(mt1, __shfl_xor_sync(0xffffffffu, mt1, 1));
            mt1 = fmaxf(mt1, __shfl_xor_sync(0xffffffffu, mt1, 2));
            const float mn0 = fmaxf(m0, mt0), mn1 = fmaxf(m1, mt1);
            const float f0 = __expf(m0 - mn0), f1 = __expf(m1 - mn1);
            m0 = mn0; m1 = mn1;

            float s0 = 0.f, s1 = 0.f;
            unsigned pu[8][4];
#pragma unroll
            for (int nt = 0; nt < 8; nt++) {
                float e0 = __expf(accS[nt][0] - mn0); s0 += e0; pu[nt][0] = f2tf(e0);
                float e1 = __expf(accS[nt][1] - mn0); s0 += e1; pu[nt][1] = f2tf(e1);
                float e2 = __expf(accS[nt][2] - mn1); s1 += e2; pu[nt][2] = f2tf(e2);
                float e3 = __expf(accS[nt][3] - mn1); s1 += e3; pu[nt][3] = f2tf(e3);
            }
            s0 += __shfl_xor_sync(0xffffffffu, s0, 1);
            s0 += __shfl_xor_sync(0xffffffffu, s0, 2);
            s1 += __shfl_xor_sync(0xffffffffu, s1, 1);
            s1 += __shfl_xor_sync(0xffffffffu, s1, 2);
            l0 = l0 * f0 + s0;
            l1 = l1 * f1 + s1;

#pragma unroll
            for (int nt = 0; nt < 16; nt++) {
                accO[nt][0] *= f0; accO[nt][1] *= f0;
                accO[nt][2] *= f1; accO[nt][3] *= f1;
            }

            // ---- phase C: O += P V, P C-frag -> A-frag via quad shuffles ----
#pragma unroll
            for (int kb = 0; kb < 8; kb++) {
                unsigned a[4];
                unsigned x0 = __shfl_sync(0xffffffffu, pu[kb][0], srcbase);
                unsigned x1 = __shfl_sync(0xffffffffu, pu[kb][1], srcbase);
                a[0] = t4p ? x1 : x0;
                unsigned x2 = __shfl_sync(0xffffffffu, pu[kb][2], srcbase);
                unsigned x3 = __shfl_sync(0xffffffffu, pu[kb][3], srcbase);
                a[1] = t4p ? x3 : x2;
                unsigned y0 = __shfl_sync(0xffffffffu, pu[kb][0], srcbase + 2);
                unsigned y1 = __shfl_sync(0xffffffffu, pu[kb][1], srcbase + 2);
                a[2] = t4p ? y1 : y0;
                unsigned y2 = __shfl_sync(0xffffffffu, pu[kb][2], srcbase + 2);
                unsigned y3 = __shfl_sync(0xffffffffu, pu[kb][3], srcbase + 2);
                a[3] = t4p ? y3 : y2;

#pragma unroll
                for (int nt = 0; nt < 16; nt++) {
                    unsigned bv[2];
                    bv[0] = Vsu[(kb * 8 + t4    ) * VLD2 + nt * 8 + g];
                    bv[1] = Vsu[(kb * 8 + t4 + 4) * VLD2 + nt * 8 + g];
                    mma_tf32(accO[nt], a, bv);
                }
            }
        }
        __syncthreads();
    }

    // ---- epilogue: normalize and store ----
    const float i0 = 1.f / l0, i1 = 1.f / l1;
    float* go0 = o + (((size_t)(b * Tc + qrow0 + g    )) * Hc + h) * Dc;
    float* go1 = o + (((size_t)(b * Tc + qrow0 + g + 8)) * Hc + h) * Dc;
#pragma unroll
    for (int nt = 0; nt < 16; nt++) {
        int c = nt * 8 + 2 * t4;
        *(float2*)(go0 + c) = make_float2(accO[nt][0] * i0, accO[nt][1] * i0);
        *(float2*)(go1 + c) = make_float2(accO[nt][2] * i1, accO[nt][3] * i1);
    }
}

// ---------------- host launcher ---------------------------------------------
extern "C" void kernel_launch(void* const* d_in, const int* in_sizes, int n_in,
                              void* d_out, int out_size)
{
    (void)in_sizes; (void)n_in; (void)out_size;
    const float* x     = (const float*)d_in[0];
    const float* freqs = (const float*)d_in[1];
    const float* Wq    = (const float*)d_in[2];
    const float* Wk    = (const float*)d_in[3];
    const float* Wv    = (const float*)d_in[4];
    const float* Wo    = (const float*)d_in[5];
    float* out = (float*)d_out;

    float *q, *k, *v, *ao;
    cudaGetSymbolAddress((void**)&q,  g_q);
    cudaGetSymbolAddress((void**)&k,  g_k);
    cudaGetSymbolAddress((void**)&v,  g_v);
    cudaGetSymbolAddress((void**)&ao, g_ao);

    cudaFuncSetAttribute(attn_kernel,
                         cudaFuncAttributeMaxDynamicSharedMemorySize,
                         ATT_SMEM_BYTES);

    // projections: q = x@Wq^T, k = x@Wk^T, v = x@Wv^T (tf32 tensor cores)
    gemm_tf32_nt<<<dim3(Cc  / 128, Mrows / 128), 128>>>(x, Wq, q,  Cc,  Cc);
    gemm_tf32_nt<<<dim3(KVC / 128, Mrows / 128), 128>>>(x, Wk, k,  KVC, Cc);
    gemm_tf32_nt<<<dim3(KVC / 128, Mrows / 128), 128>>>(x, Wv, v,  KVC, Cc);

    // RoPE (in place, fp32)
    rope_kernel<<<(Mrows * Hc   * 64) / 256, 256>>>(q, freqs, Hc);
    rope_kernel<<<(Mrows * HKVc * 64) / 256, 256>>>(k, freqs, HKVc);

    // causal GQA flash attention (tf32 mma, register-resident softmax)
    attn_kernel<<<dim3(Tc / 128, Hc, Bc), 256, ATT_SMEM_BYTES>>>(q, k, v, ao);

    // output projection: out = ao @ Wo^T
    gemm_tf32_nt<<<dim3(Cc / 128, Mrows / 128), 128>>>(ao, Wo, out, Cc, Cc);
}

// round 9
// speedup vs baseline: 6.8490x; 1.8621x over previous
#include <cuda_runtime.h>
#include <cuda_fp16.h>
#include <math.h>

#define Bc   4
#define Tc   2048
#define Cc   2048
#define Hc   16
#define HKVc 4
#define Dc   128
#define Mrows (Bc*Tc)          // 8192
#define KVC  (HKVc*Dc)         // 512

// ---------------- scratch (device globals; no runtime allocation) -----------
__device__ __half g_xh [(size_t)Mrows*Cc];
__device__ __half g_wqh[(size_t)Cc*Cc];
__device__ __half g_wkh[(size_t)KVC*Cc];
__device__ __half g_wvh[(size_t)KVC*Cc];
__device__ __half g_woh[(size_t)Cc*Cc];
__device__ __half g_qh [(size_t)Mrows*Cc];   // [b,t,h,d] (Wq pre-scaled by 1/sqrt(d))
__device__ __half g_kh [(size_t)Mrows*KVC];  // [b,t,hkv,d]
__device__ __half g_vh [(size_t)Mrows*KVC];
__device__ __half g_aoh[(size_t)Mrows*Cc];   // attention output

// ---------------- helpers -----------------------------------------------------
__device__ __forceinline__ unsigned packh2(float x, float y) {
    __half2 h = __floats2half2_rn(x, y);
    return *reinterpret_cast<unsigned*>(&h);
}

// D(16x8 fp32) += A(16x16 fp16, row) * B(16x8 fp16, col)
__device__ __forceinline__ void mma_f16(float* d, const unsigned* a, const unsigned* b) {
    asm volatile(
        "mma.sync.aligned.m16n8k16.row.col.f32.f16.f16.f32 "
        "{%0,%1,%2,%3},{%4,%5,%6,%7},{%8,%9},{%0,%1,%2,%3};"
        : "+f"(d[0]), "+f"(d[1]), "+f"(d[2]), "+f"(d[3])
        : "r"(a[0]), "r"(a[1]), "r"(a[2]), "r"(a[3]), "r"(b[0]), "r"(b[1]));
}

#define LDSM_X4_T(r0, r1, r2, r3, addr) \
    asm volatile("ldmatrix.sync.aligned.m8n8.x4.trans.shared.b16 {%0,%1,%2,%3}, [%4];" \
                 : "=r"(r0), "=r"(r1), "=r"(r2), "=r"(r3) : "r"(addr))

// ---------------- fp32 -> fp16 convert (with optional scale) -----------------
__global__ void cvt16_kernel(const float* __restrict__ s, __half* __restrict__ d,
                             float scale)
{
    int idx = blockIdx.x * blockDim.x + threadIdx.x;  // exact grid
    float4 v = ((const float4*)s)[idx];
    ((__half2*)d)[2*idx    ] = __floats2half2_rn(v.x * scale, v.y * scale);
    ((__half2*)d)[2*idx + 1] = __floats2half2_rn(v.z * scale, v.w * scale);
}

// ---------------- fp16 GEMM, C[m,n] = sum_k A[m,k]*B[n,k] (NT) ---------------
// 128x128 tile, BK=32, 128 threads (4 warps, 2x2 of 64x64 warp tiles),
// double-buffered smem (direct fp16 copies), m16n8k16.
// Tile row = 32 halfs = 16 words; pitch 20 words.
#define WP 20

template<int OUT16>
__global__ void __launch_bounds__(128, 2)
gemm_f16_nt(const __half* __restrict__ A, const __half* __restrict__ Bm,
            void* __restrict__ Cm, int N, int K)
{
    __shared__ unsigned As[2][128 * WP];
    __shared__ unsigned Bs[2][128 * WP];

    const int tid = threadIdx.x;
    const int wid = tid >> 5, lane = tid & 31;
    const int g   = lane >> 2, t4 = lane & 3;
    const int wm  = wid >> 1,  wn = wid & 1;
    const int bm  = blockIdx.y * 128, bn = blockIdx.x * 128;

    float acc[4][8][4];
#pragma unroll
    for (int i = 0; i < 4; i++)
#pragma unroll
        for (int j = 0; j < 8; j++)
#pragma unroll
            for (int r = 0; r < 4; r++) acc[i][j][r] = 0.f;

    uint4 va[4], vb[4];

    // prologue: tile k0=0
#pragma unroll
    for (int l = 0; l < 4; l++) {
        int f = tid + l * 128, row = f >> 2, ch = f & 3;
        va[l] = *(const uint4*)(A  + (size_t)(bm + row) * K + ch * 8);
        vb[l] = *(const uint4*)(Bm + (size_t)(bn + row) * K + ch * 8);
    }
#pragma unroll
    for (int l = 0; l < 4; l++) {
        int f = tid + l * 128, row = f >> 2, ch = f & 3;
        *(uint4*)&As[0][row * WP + ch * 4] = va[l];
        *(uint4*)&Bs[0][row * WP + ch * 4] = vb[l];
    }
    __syncthreads();

    int buf = 0;
    for (int k0 = 0; k0 < K; k0 += 32) {
        const bool has_next = (k0 + 32) < K;
        if (has_next) {
#pragma unroll
            for (int l = 0; l < 4; l++) {
                int f = tid + l * 128, row = f >> 2, ch = f & 3;
                va[l] = *(const uint4*)(A  + (size_t)(bm + row) * K + k0 + 32 + ch * 8);
                vb[l] = *(const uint4*)(Bm + (size_t)(bn + row) * K + k0 + 32 + ch * 8);
            }
        }

#pragma unroll
        for (int ks = 0; ks < 2; ks++) {
            unsigned a[4][4], b[8][2];
#pragma unroll
            for (int mt = 0; mt < 4; mt++) {
                int m = wm * 64 + mt * 16;
                a[mt][0] = As[buf][(m + g    ) * WP + ks * 8 + t4];
                a[mt][1] = As[buf][(m + g + 8) * WP + ks * 8 + t4];
                a[mt][2] = As[buf][(m + g    ) * WP + ks * 8 + t4 + 4];
                a[mt][3] = As[buf][(m + g + 8) * WP + ks * 8 + t4 + 4];
            }
#pragma unroll
            for (int nt = 0; nt < 8; nt++) {
                int n = wn * 64 + nt * 8;
                b[nt][0] = Bs[buf][(n + g) * WP + ks * 8 + t4];
                b[nt][1] = Bs[buf][(n + g) * WP + ks * 8 + t4 + 4];
            }
#pragma unroll
            for (int mt = 0; mt < 4; mt++)
#pragma unroll
                for (int nt = 0; nt < 8; nt++)
                    mma_f16(acc[mt][nt], a[mt], b[nt]);
        }

        if (has_next) {
#pragma unroll
            for (int l = 0; l < 4; l++) {
                int f = tid + l * 128, row = f >> 2, ch = f & 3;
                *(uint4*)&As[buf ^ 1][row * WP + ch * 4] = va[l];
                *(uint4*)&Bs[buf ^ 1][row * WP + ch * 4] = vb[l];
            }
        }
        __syncthreads();
        buf ^= 1;
    }

#pragma unroll
    for (int mt = 0; mt < 4; mt++) {
        int r0 = bm + wm * 64 + mt * 16 + g;
#pragma unroll
        for (int nt = 0; nt < 8; nt++) {
            int c = bn + wn * 64 + nt * 8 + 2 * t4;
            if (OUT16) {
                unsigned* o = (unsigned*)Cm;
                o[((size_t)r0 * N + c) >> 1] =
                    packh2(acc[mt][nt][0], acc[mt][nt][1]);
                o[((size_t)(r0 + 8) * N + c) >> 1] =
                    packh2(acc[mt][nt][2], acc[mt][nt][3]);
            } else {
                float* o = (float*)Cm;
                *(float2*)(o + (size_t)r0 * N + c) =
                    make_float2(acc[mt][nt][0], acc[mt][nt][1]);
                *(float2*)(o + (size_t)(r0 + 8) * N + c) =
                    make_float2(acc[mt][nt][2], acc[mt][nt][3]);
            }
        }
    }
}

// ---------------- RoPE (NeoX rotate-half), in place on fp16 ------------------
__global__ void rope_h_kernel(__half* __restrict__ p, const float* __restrict__ freqs,
                              int nh)
{
    int idx = blockIdx.x * blockDim.x + threadIdx.x;
    int pr = idx & 63;
    int h  = (idx >> 6) % nh;
    int bt = idx / (64 * nh);
    int t  = bt & (Tc - 1);
    float c = freqs[(t * 64 + pr) * 2 + 0];
    float s = freqs[(t * 64 + pr) * 2 + 1];
    __half* base = p + ((size_t)bt * nh + h) * Dc;
    float u0 = __half2float(base[pr]);
    float u1 = __half2float(base[pr + 64]);
    base[pr]      = __float2half_rn(u0 * c - u1 * s);
    base[pr + 64] = __float2half_rn(u1 * c + u0 * s);
}

// ---------------- flash attention, fp16 mma, register-resident ---------------
// 128 q-rows per block, 8 warps (16 rows each), 64-row KV tiles.
// Q A-fragments in registers; P C-frag -> A-frag with zero shuffles (fp16);
// V consumed via ldmatrix.x4.trans.
// K/V smem: row = 128 halfs = 64 words data + 4 pad = pitch 68 words (272 B).
#define KVP 68

__global__ void __launch_bounds__(256, 1)
attn_kernel(const __half* __restrict__ q, const __half* __restrict__ k,
            const __half* __restrict__ v, __half* __restrict__ o)
{
    __shared__ unsigned Ksu[64 * KVP];
    __shared__ unsigned Vsu[64 * KVP];

    const int qt = blockIdx.x, h = blockIdx.y, b = blockIdx.z;
    const int kvh = h >> 2;
    const int tid = threadIdx.x;
    const int wid = tid >> 5, lane = tid & 31;
    const int g   = lane >> 2, t4 = lane & 3;

    const int qrow0 = qt * 128 + wid * 16;   // this warp's first q row

    // per-lane ldmatrix base address into Vsu (mat = lane>>3)
    const unsigned vbase = (unsigned)__cvta_generic_to_shared(Vsu);
    const int mat = lane >> 3;
    const unsigned vlane = vbase + (unsigned)(((mat & 1) * 8 + (lane & 7)) * (KVP * 4)
                                              + (mat >> 1) * 16);

    // ---- Q fragments in registers (scale folded into Wq) ----
    unsigned qf[8][4];
    {
        const __half* q0 = q + (((size_t)(b * Tc + qrow0 + g    )) * Hc + h) * Dc;
        const __half* q1 = q0 + (size_t)8 * Hc * Dc;
#pragma unroll
        for (int kb = 0; kb < 8; kb++) {
            qf[kb][0] = *(const unsigned*)(q0 + kb * 16 + 2 * t4);
            qf[kb][1] = *(const unsigned*)(q1 + kb * 16 + 2 * t4);
            qf[kb][2] = *(const unsigned*)(q0 + kb * 16 + 2 * t4 + 8);
            qf[kb][3] = *(const unsigned*)(q1 + kb * 16 + 2 * t4 + 8);
        }
    }

    float accO[16][4];
#pragma unroll
    for (int nt = 0; nt < 16; nt++)
#pragma unroll
        for (int r = 0; r < 4; r++) accO[nt][r] = 0.f;

    float m0 = -1e30f, m1 = -1e30f, l0 = 0.f, l1 = 0.f;

    const int nkt = 2 * qt + 2;
    for (int kt = 0; kt < nkt; kt++) {
        // ---- cooperative K/V tile load (fp16 direct copy) ----
        {
            const int tbase = kt * 64;
            const __half* gk = k + (((size_t)(b * Tc + tbase)) * HKVc + kvh) * Dc;
            const __half* gv = v + (((size_t)(b * Tc + tbase)) * HKVc + kvh) * Dc;
#pragma unroll
            for (int l = 0; l < 4; l++) {
                int f = tid + l * 256;         // 0..1023
                int row = f >> 4;              // 0..63
                int ch  = f & 15;              // 16B chunks (16*16B = 256B/row)
                *(uint4*)&Ksu[row * KVP + ch * 4] =
                    *(const uint4*)(gk + (size_t)row * (HKVc * Dc) + ch * 8);
                *(uint4*)&Vsu[row * KVP + ch * 4] =
                    *(const uint4*)(gv + (size_t)row * (HKVc * Dc) + ch * 8);
            }
        }
        __syncthreads();

        if (kt * 64 <= qrow0 + 15) {   // warp has unmasked work in this tile
            // ---- phase A: S(16x64) = Q K^T ----
            float accS[8][4];
#pragma unroll
            for (int nt = 0; nt < 8; nt++)
#pragma unroll
                for (int r = 0; r < 4; r++) accS[nt][r] = 0.f;

#pragma unroll
            for (int kb = 0; kb < 8; kb++) {
                unsigned bb[8][2];
#pragma unroll
                for (int nt = 0; nt < 8; nt++) {
                    bb[nt][0] = Ksu[(nt * 8 + g) * KVP + kb * 8 + t4];
                    bb[nt][1] = Ksu[(nt * 8 + g) * KVP + kb * 8 + t4 + 4];
                }
#pragma unroll
                for (int nt = 0; nt < 8; nt++)
                    mma_f16(accS[nt], qf[kb], bb[nt]);
            }

            // ---- causal mask (register) ----
            if (kt * 64 + 63 > qrow0) {
                const int r0 = qrow0 + g, r1 = r0 + 8;
#pragma unroll
                for (int nt = 0; nt < 8; nt++) {
                    int c0 = kt * 64 + nt * 8 + 2 * t4;
                    if (c0     > r0) accS[nt][0] = -1e30f;
                    if (c0 + 1 > r0) accS[nt][1] = -1e30f;
                    if (c0     > r1) accS[nt][2] = -1e30f;
                    if (c0 + 1 > r1) accS[nt][3] = -1e30f;
                }
            }

            // ---- register online softmax (quad = one row pair) ----
            float mt0 = -1e30f, mt1 = -1e30f;
#pragma unroll
            for (int nt = 0; nt < 8; nt++) {
                mt0 = fmaxf(mt0, fmaxf(accS[nt][0], accS[nt][1]));
                mt1 = fmaxf(mt1, fmaxf(accS[nt][2], accS[nt][3]));
            }
            mt0 = fmaxf(mt0, __shfl_xor_sync(0xffffffffu, mt0, 1));
            mt0 = fmaxf(mt0, __shfl_xor_sync(0xffffffffu, mt0, 2));
            mt1 = fmaxf(mt1, __shfl_xor_sync(0xffffffffu, mt1, 1));
            mt1 = fmaxf(mt1, __shfl_xor_sync(0xffffffffu, mt1, 2));
            const float mn0 = fmaxf(m0, mt0), mn1 = fmaxf(m1, mt1);
            const float f0 = __expf(m0 - mn0), f1 = __expf(m1 - mn1);
            m0 = mn0; m1 = mn1;

            float s0 = 0.f, s1 = 0.f;
#pragma unroll
            for (int nt = 0; nt < 8; nt++) {
                accS[nt][0] = __expf(accS[nt][0] - mn0); s0 += accS[nt][0];
                accS[nt][1] = __expf(accS[nt][1] - mn0); s0 += accS[nt][1];
                accS[nt][2] = __expf(accS[nt][2] - mn1); s1 += accS[nt][2];
                accS[nt][3] = __expf(accS[nt][3] - mn1); s1 += accS[nt][3];
            }
            s0 += __shfl_xor_sync(0xffffffffu, s0, 1);
            s0 += __shfl_xor_sync(0xffffffffu, s0, 2);
            s1 += __shfl_xor_sync(0xffffffffu, s1, 1);
            s1 += __shfl_xor_sync(0xffffffffu, s1, 2);
            l0 = l0 * f0 + s0;
            l1 = l1 * f1 + s1;

#pragma unroll
            for (int nt = 0; nt < 16; nt++) {
                accO[nt][0] *= f0; accO[nt][1] *= f0;
                accO[nt][2] *= f1; accO[nt][3] *= f1;
            }

            // ---- phase C: O += P V (zero-shuffle P->A, ldmatrix.trans V) ----
#pragma unroll
            for (int kb = 0; kb < 4; kb++) {
                unsigned pa[4];
                pa[0] = packh2(accS[2*kb  ][0], accS[2*kb  ][1]);
                pa[1] = packh2(accS[2*kb  ][2], accS[2*kb  ][3]);
                pa[2] = packh2(accS[2*kb+1][0], accS[2*kb+1][1]);
                pa[3] = packh2(accS[2*kb+1][2], accS[2*kb+1][3]);
#pragma unroll
                for (int nt2 = 0; nt2 < 8; nt2++) {
                    unsigned r0, r1, r2, r3;
                    unsigned addr = vlane + (unsigned)(kb * 16 * (KVP * 4) + nt2 * 32);
                    LDSM_X4_T(r0, r1, r2, r3, addr);
                    unsigned b0[2] = {r0, r1}, b1[2] = {r2, r3};
                    mma_f16(accO[2*nt2    ], pa, b0);
                    mma_f16(accO[2*nt2 + 1], pa, b1);
                }
            }
        }
        __syncthreads();
    }

    // ---- epilogue: normalize, convert to fp16, store ----
    const float i0 = 1.f / l0, i1 = 1.f / l1;
    unsigned* go0 = (unsigned*)(o + (((size_t)(b * Tc + qrow0 + g    )) * Hc + h) * Dc);
    unsigned* go1 = (unsigned*)(o + (((size_t)(b * Tc + qrow0 + g + 8)) * Hc + h) * Dc);
#pragma unroll
    for (int nt = 0; nt < 16; nt++) {
        int cw = (nt * 8 + 2 * t4) >> 1;
        go0[cw] = packh2(accO[nt][0] * i0, accO[nt][1] * i0);
        go1[cw] = packh2(accO[nt][2] * i1, accO[nt][3] * i1);
    }
}

// ---------------- host launcher ---------------------------------------------
extern "C" void kernel_launch(void* const* d_in, const int* in_sizes, int n_in,
                              void* d_out, int out_size)
{
    (void)in_sizes; (void)n_in; (void)out_size;
    const float* x     = (const float*)d_in[0];
    const float* freqs = (const float*)d_in[1];
    const float* Wq    = (const float*)d_in[2];
    const float* Wk    = (const float*)d_in[3];
    const float* Wv    = (const float*)d_in[4];
    const float* Wo    = (const float*)d_in[5];
    float* out = (float*)d_out;

    __half *xh, *wqh, *wkh, *wvh, *woh, *qh, *kh, *vh, *aoh;
    cudaGetSymbolAddress((void**)&xh,  g_xh);
    cudaGetSymbolAddress((void**)&wqh, g_wqh);
    cudaGetSymbolAddress((void**)&wkh, g_wkh);
    cudaGetSymbolAddress((void**)&wvh, g_wvh);
    cudaGetSymbolAddress((void**)&woh, g_woh);
    cudaGetSymbolAddress((void**)&qh,  g_qh);
    cudaGetSymbolAddress((void**)&kh,  g_kh);
    cudaGetSymbolAddress((void**)&vh,  g_vh);
    cudaGetSymbolAddress((void**)&aoh, g_aoh);

    const float qscale = 0.08838834764831845f;  // 1/sqrt(128)

    // fp32 -> fp16 staging (scale folded into Wq)
    cvt16_kernel<<<((size_t)Mrows*Cc/4)/256, 256>>>(x,  xh,  1.f);
    cvt16_kernel<<<((size_t)Cc*Cc/4)/256,    256>>>(Wq, wqh, qscale);
    cvt16_kernel<<<((size_t)KVC*Cc/4)/256,   256>>>(Wk, wkh, 1.f);
    cvt16_kernel<<<((size_t)KVC*Cc/4)/256,   256>>>(Wv, wvh, 1.f);
    cvt16_kernel<<<((size_t)Cc*Cc/4)/256,    256>>>(Wo, woh, 1.f);

    // projections (fp16 in, fp16 out)
    gemm_f16_nt<1><<<dim3(Cc  / 128, Mrows / 128), 128>>>(xh, wqh, qh, Cc,  Cc);
    gemm_f16_nt<1><<<dim3(KVC / 128, Mrows / 128), 128>>>(xh, wkh, kh, KVC, Cc);
    gemm_f16_nt<1><<<dim3(KVC / 128, Mrows / 128), 128>>>(xh, wvh, vh, KVC, Cc);

    // RoPE (in place, fp16 storage / fp32 math)
    rope_h_kernel<<<(Mrows * Hc   * 64) / 256, 256>>>(qh, freqs, Hc);
    rope_h_kernel<<<(Mrows * HKVc * 64) / 256, 256>>>(kh, freqs, HKVc);

    // causal GQA flash attention (fp16 mma)
    attn_kernel<<<dim3(Tc / 128, Hc, Bc), 256>>>(qh, kh, vh, aoh);

    // output projection (fp16 in, fp32 out)
    gemm_f16_nt<0><<<dim3(Cc / 128, Mrows / 128), 128>>>(aoh, woh, out, Cc, Cc);
}